// round 17
// baseline (speedup 1.0000x reference)
#include <cuda_runtime.h>
#include <cuda_fp16.h>
#include <cstdint>

// ---------------------------------------------------------------------------
// Problem constants
// ---------------------------------------------------------------------------
#define Nn 5570          // nodes
#define NT 256           // live aggregation columns = B(16) * D(4) * 4
#define MP 5632          // M padded: 44 tiles of 128
#define KK 5632          // K padded
#define MT 44            // row tiles
#define CT 2             // col tiles (2 x 128 = 256)
#define KSLICES 3        // K split: iters 30/30/28 of BK=64
#define NTILE 3916       // upper-triangle 64x64 tiles: 88*89/2
#define NTBLK 352        // T-part blocks (5632/16)
#define PSP 88           // psum pitch (tiles per dim)

// ---------------------------------------------------------------------------
// Device scratch
// ---------------------------------------------------------------------------
__device__ __align__(128) uint32_t g_A[(size_t)MP * KK / 2];
__device__ __align__(128) uint32_t g_B[(size_t)KK * NT / 2];
__device__ float g_T0[(size_t)KK * NT];     // k=0 (identity) per-node partials
__device__ float g_rowinv[MP];
__device__ float g_Agg[(size_t)KSLICES * MP * NT];  // K-slice partials
__device__ float g_psum[(size_t)MP * PSP];  // per-tile rowsum partials
__device__ float g_scl[MP];                 // 2^(-M2_i) row scales
__device__ __align__(16) float g_Epad[MP * 4];
__device__ unsigned int g_gmax2_bits = 0u;  // max |e_m|^2 bits (atomicMax:
                                            // order-independent, deterministic)

// ---------------------------------------------------------------------------
// Helpers
// ---------------------------------------------------------------------------
__device__ __forceinline__ uint32_t smem_u32(const void* p) {
    uint32_t a;
    asm("{ .reg .u64 t; cvta.to.shared.u64 t, %1; cvt.u32.u64 %0, t; }" : "=r"(a) : "l"(p));
    return a;
}

// 2^t on the FMA pipe, |t| < ~120. ~4e-5 relative error.
__device__ __forceinline__ float fexp2g(float t) {
    float km = t + 12582912.0f;                 // round-to-nearest magic
    int   ki = __float_as_int(km);
    float f  = t - (km - 12582912.0f);          // f in [-0.5, 0.5]
    float p  = 9.6180691e-3f;
    p = fmaf(p, f, 5.5504109e-2f);
    p = fmaf(p, f, 2.4022651e-1f);
    p = fmaf(p, f, 6.9314718e-1f);
    p = fmaf(p, f, 1.0f);
    float sc = __int_as_float((ki - (0x4B400000 - 127)) << 23);  // 2^round(t)
    return p * sc;
}

#define LOG2E 1.4426950408889634f

// ---------------------------------------------------------------------------
// Micro-kernel 1: global max of |e_m|^2
// ---------------------------------------------------------------------------
__global__ void __launch_bounds__(256) normmax_kernel(const float* __restrict__ E) {
    int m = blockIdx.x * 256 + threadIdx.x;
    float v = 0.f;
    if (m < Nn) {
        float4 em = ((const float4*)E)[m];
        v = fmaf(em.x, em.x, fmaf(em.y, em.y, fmaf(em.z, em.z, em.w * em.w)));
    }
    #pragma unroll
    for (int o = 16; o > 0; o >>= 1) v = fmaxf(v, __shfl_xor_sync(0xffffffffu, v, o));
    if ((threadIdx.x & 31) == 0)
        atomicMax(&g_gmax2_bits, __float_as_uint(v));
}

// ---------------------------------------------------------------------------
// Micro-kernel 2: per-row scale 2^(-M2_i) and zero-padded E copy
// ---------------------------------------------------------------------------
__global__ void __launch_bounds__(256) scl_kernel(const float* __restrict__ E) {
    int i = blockIdx.x * 256 + threadIdx.x;
    if (i >= MP) return;
    float4 e = make_float4(0.f, 0.f, 0.f, 0.f);
    float scl = 1.f;
    if (i < Nn) {
        e = ((const float4*)E)[i];
        float en2 = fmaf(e.x, e.x, fmaf(e.y, e.y, fmaf(e.z, e.z, e.w * e.w)));
        float gmax2 = __uint_as_float(g_gmax2_bits);
        float M2 = sqrtf(en2 * gmax2) * LOG2E;   // Cauchy-Schwarz bound, log2 units
        scl = fexp2g(-M2);
    }
    ((float4*)g_Epad)[i] = e;
    g_scl[i] = scl;
}

// ---------------------------------------------------------------------------
// Kernel 3 (fused): blocks [0, NTBLK): T^T (k=1 -> fp16 B) + T0 (k=0 -> fp32).
//   blocks [NTBLK, NTBLK+NTILE): symmetric exp tiles. Tile (ti<=tj) computes
//   q = 2^(log2e*relu(z)) once, writes P_ij = q*scl_i and P_ji = q*scl_j
//   (transposed via SMEM), plus row/col partial sums into g_psum.
// ---------------------------------------------------------------------------
__global__ void __launch_bounds__(256) fused_prep_kernel(
    const float* __restrict__ x,
    const float* __restrict__ wg, const float* __restrict__ wu)
{
    __shared__ __align__(16) char sbuf[40640];
    int tid = threadIdx.x;
    if (blockIdx.x >= NTBLK) {
        // ------------------ symmetric exp tile ------------------
        int bx = blockIdx.x - NTBLK;
        int tj = (int)((sqrtf(8.0f * bx + 1.0f) - 1.0f) * 0.5f);
        while ((tj + 1) * (tj + 2) / 2 <= bx) tj++;
        while (tj * (tj + 1) / 2 > bx) tj--;
        int ti = bx - tj * (tj + 1) / 2;

        float (*sEi)[4] = (float(*)[4])(sbuf);            // 1024 B (log2e-scaled)
        float (*sEj)[4] = (float(*)[4])(sbuf + 1024);     // 1024 B (raw)
        float* sScli = (float*)(sbuf + 2048);             // 256 B
        float* sSclj = (float*)(sbuf + 2304);             // 256 B
        __half (*sT)[66] = (__half(*)[66])(sbuf + 2560);  // 8448 B transpose

        {
            int rr = tid >> 2, qq = tid & 3;
            sEi[rr][qq] = g_Epad[(ti * 64 + rr) * 4 + qq] * LOG2E;
            sEj[rr][qq] = g_Epad[(tj * 64 + rr) * 4 + qq];
            if (tid < 64) sScli[tid] = g_scl[ti * 64 + tid];
            else if (tid < 128) sSclj[tid - 64] = g_scl[tj * 64 + (tid - 64)];
        }
        __syncthreads();

        int r = tid >> 2;        // row within ti tile
        int cq = tid & 3;        // column quarter (16 cols)
        float ex = sEi[r][0], ey = sEi[r][1], ez = sEi[r][2], ew = sEi[r][3];
        float scli = sScli[r];
        float q16[16];
        float rsum = 0.f;
        #pragma unroll
        for (int c = 0; c < 16; c++) {
            int j = cq * 16 + c;
            float4 ej = *(const float4*)&sEj[j][0];
            float t = fmaf(ex, ej.x, fmaf(ey, ej.y, fmaf(ez, ej.z, ew * ej.w)));
            t = fmaxf(t, 0.f);
            float q = fexp2g(t);
            q16[c] = q;
            rsum += q;
            sT[j][r] = __float2half_rn(q * sSclj[j]);
        }
        // direct (i, j) write: row ti*64+r, cols tj*64 + cq*16 .. +15
        {
            uint32_t w[8];
            #pragma unroll
            for (int c = 0; c < 8; c++) {
                __half2 h = __floats2half2_rn(q16[2 * c] * scli, q16[2 * c + 1] * scli);
                w[c] = *reinterpret_cast<uint32_t*>(&h);
            }
            uint32_t* dst = g_A + (size_t)(ti * 64 + r) * (KK / 2) + tj * 32 + cq * 8;
            *(uint4*)dst = make_uint4(w[0], w[1], w[2], w[3]);
            *(uint4*)(dst + 4) = make_uint4(w[4], w[5], w[6], w[7]);
        }
        // row partial sum (scaled)
        rsum += __shfl_xor_sync(0xffffffffu, rsum, 1);
        rsum += __shfl_xor_sync(0xffffffffu, rsum, 2);
        if (cq == 0) g_psum[(size_t)(ti * 64 + r) * PSP + tj] = rsum * scli;
        __syncthreads();
        // transposed write + column partial sum: row tj*64+r, cols ti*64+cq*16
        {
            float csum = 0.f;
            uint32_t w[8];
            const __half* src = &sT[r][cq * 16];
            #pragma unroll
            for (int c = 0; c < 8; c++) {
                __half2 h2 = *(const __half2*)(src + 2 * c);
                float2 f2 = __half22float2(h2);
                csum += f2.x + f2.y;
                w[c] = *reinterpret_cast<uint32_t*>(&h2);
            }
            uint32_t* dst = g_A + (size_t)(tj * 64 + r) * (KK / 2) + ti * 32 + cq * 8;
            *(uint4*)dst = make_uint4(w[0], w[1], w[2], w[3]);
            *(uint4*)(dst + 4) = make_uint4(w[4], w[5], w[6], w[7]);
            csum += __shfl_xor_sync(0xffffffffu, csum, 1);
            csum += __shfl_xor_sync(0xffffffffu, csum, 2);
            if (cq == 0 && ti != tj)
                g_psum[(size_t)(tj * 64 + r) * PSP + ti] = csum;
        }
    } else {
        // ------------------ T parts: 16 m-rows x 16 batches ------------------
        float (*sW1)[16] = (float(*)[16])(sbuf);            // 2240 B
        float (*sW0)[16] = (float(*)[16])(sbuf + 2240);     // 2240 B
        float (*sx)[565] = (float(*)[565])(sbuf + 4480);    // 36160 B
        for (int idx = tid; idx < 35 * 16; idx += 256) {
            int i = idx / 16, j = idx % 16, d = j / 4, o = j % 4;
            sW1[i][j] = (o < 2) ? wg[((d * 2 + 1) * 37 + i) * 4 + (o + 2)]
                                : wu[((d * 2 + 1) * 37 + i) * 2 + (o - 2)];
            sW0[i][j] = (o < 2) ? wg[((d * 2) * 37 + i) * 4 + (o + 2)]
                                : wu[((d * 2) * 37 + i) * 2 + (o - 2)];
        }
        int m0 = blockIdx.x * 16;
        if (m0 + 16 <= Nn) {
            for (int j = tid; j < 16 * 560; j += 256) {
                int b = j / 560, rr = j - b * 560;
                sx[b][rr] = x[((size_t)b * Nn + m0) * 35 + rr];
            }
        } else {
            for (int j = tid; j < 16 * 560; j += 256) {
                int b = j / 560, rr = j - b * 560;
                int m = m0 + rr / 35;
                sx[b][rr] = (m < Nn) ? x[((size_t)b * Nn + m0) * 35 + rr] : 0.f;
            }
        }
        __syncthreads();

        int ml = tid >> 4;
        int m  = m0 + ml;
        int b  = tid & 15;
        float ak[16], az[16];
        #pragma unroll
        for (int j = 0; j < 16; j++) { ak[j] = 0.f; az[j] = 0.f; }
        if (m < Nn) {
            const float* xs = &sx[b][ml * 35];
            for (int i = 0; i < 35; i++) {
                float xv = xs[i];
                #pragma unroll
                for (int j = 0; j < 16; j++) {
                    ak[j] = fmaf(xv, sW1[i][j], ak[j]);
                    az[j] = fmaf(xv, sW0[i][j], az[j]);
                }
            }
        }
        size_t baseB = (size_t)m * (NT / 2) + b * 8;
        #pragma unroll
        for (int j = 0; j < 8; j++) {
            __half2 h = __floats2half2_rn(ak[2 * j], ak[2 * j + 1]);
            g_B[baseB + j] = *reinterpret_cast<uint32_t*>(&h);
        }
        float* t0p = g_T0 + (size_t)m * NT + b * 16;
        #pragma unroll
        for (int j = 0; j < 4; j++) {
            float4 v = make_float4(az[4 * j], az[4 * j + 1], az[4 * j + 2], az[4 * j + 3]);
            *(float4*)&t0p[4 * j] = v;
        }
    }
}

// ---------------------------------------------------------------------------
// Kernel 4: deterministic rowsum reduce. rowsum_i = sum_t psum[i][t]
//           - 62*scl_i (exact phantom-column correction); rowinv = 1/rowsum.
// ---------------------------------------------------------------------------
__global__ void __launch_bounds__(256) rowsum_kernel() {
    int wid = threadIdx.x >> 5, lane = threadIdx.x & 31;
    int i = blockIdx.x * 8 + wid;
    const float* p = g_psum + (size_t)i * PSP;
    float s = p[lane] + p[lane + 32];
    if (lane < PSP - 64) s += p[lane + 64];
    #pragma unroll
    for (int o = 16; o > 0; o >>= 1) s += __shfl_xor_sync(0xffffffffu, s, o);
    if (lane == 0)
        g_rowinv[i] = 1.f / (s - 62.f * g_scl[i]);
}

// ---------------------------------------------------------------------------
// Kernel 5: GEMM partials (unchanged from R16).
// ---------------------------------------------------------------------------
#define APITCH3 144
#define BPITCH3 272
#define ASZ3 (128 * APITCH3)
#define BSZ3 (64 * BPITCH3)
#define BOFF3 ASZ3
#define STAGE3 (ASZ3 + BSZ3)
#define NSTG3 3
#define SMEM_TOTAL3 (NSTG3 * STAGE3)

__device__ __forceinline__ void cpasync16(uint32_t dst, const void* src) {
    asm volatile("cp.async.cg.shared.global [%0], [%1], 16;" :: "r"(dst), "l"(src));
}
__device__ __forceinline__ void ldsm4(uint32_t* r, uint32_t addr) {
    asm volatile("ldmatrix.sync.aligned.m8n8.x4.shared.b16 {%0,%1,%2,%3}, [%4];"
        : "=r"(r[0]), "=r"(r[1]), "=r"(r[2]), "=r"(r[3]) : "r"(addr));
}
__device__ __forceinline__ void ldsm4t(uint32_t* r, uint32_t addr) {
    asm volatile("ldmatrix.sync.aligned.m8n8.x4.trans.shared.b16 {%0,%1,%2,%3}, [%4];"
        : "=r"(r[0]), "=r"(r[1]), "=r"(r[2]), "=r"(r[3]) : "r"(addr));
}
#define MMA(acc, a, b) \
    asm volatile("mma.sync.aligned.m16n8k16.row.col.f32.f16.f16.f32 " \
        "{%0,%1,%2,%3}, {%4,%5,%6,%7}, {%8,%9}, {%0,%1,%2,%3};" \
        : "+f"((acc)[0]), "+f"((acc)[1]), "+f"((acc)[2]), "+f"((acc)[3]) \
        : "r"((a)[0]), "r"((a)[1]), "r"((a)[2]), "r"((a)[3]), \
          "r"((b)[0]), "r"((b)[1]))

__global__ void __launch_bounds__(128, 2) gemm_mma_kernel() {
    extern __shared__ __align__(128) char smem[];
    uint32_t sb = smem_u32(smem);
    int tid = threadIdx.x, wid = tid >> 5, lid = tid & 31;
    int rt = blockIdx.x, ct = blockIdx.y, ks = blockIdx.z;
    int kbase = ks * 1920;
    int nit = (ks == 2) ? 28 : 30;
    int warpM = (wid >> 1) * 64;
    int warpN = (wid & 1) * 64;

    const char* Ab = (const char*)g_A + ((size_t)rt * 128 * KK + (size_t)kbase) * 2;
    const char* Bb = (const char*)g_B + ((size_t)kbase * NT + (size_t)ct * 128) * 2;
    float* Aggp = g_Agg + (size_t)ks * MP * NT;

    float acc[4][8][4];
    #pragma unroll
    for (int mi = 0; mi < 4; mi++)
        #pragma unroll
        for (int nj = 0; nj < 8; nj++)
            #pragma unroll
            for (int q = 0; q < 4; q++) acc[mi][nj][q] = 0.f;

    int aRow = lid & 15, aK = lid >> 4;
    int bK = (lid & 7) + ((lid >> 3) & 1) * 8;
    int bN = ((lid >> 4) & 1) * 8;

    auto issue = [&](int s, int k0) {
        uint32_t d = sb + s * STAGE3;
        #pragma unroll
        for (int i = 0; i < 8; i++) {
            int ci = tid + i * 128;
            int ar = ci >> 3, ak = ci & 7;
            cpasync16(d + ar * APITCH3 + ak * 16,
                      Ab + ((size_t)ar * KK + k0 + ak * 8) * 2);
        }
        #pragma unroll
        for (int i = 0; i < 8; i++) {
            int ci = tid + i * 128;
            int bk = ci >> 4, bc = ci & 15;
            cpasync16(d + BOFF3 + bk * BPITCH3 + bc * 16,
                      Bb + ((size_t)(k0 + bk) * NT + bc * 8) * 2);
        }
    };
    auto loadA = [&](uint32_t st, int k16, uint32_t (*a)[4]) {
        #pragma unroll
        for (int mi = 0; mi < 4; mi++)
            ldsm4(a[mi], st + (warpM + mi * 16 + aRow) * APITCH3 + k16 * 32 + aK * 16);
    };
    auto loadB = [&](uint32_t st, int k16, uint32_t (*b)[4]) {
        #pragma unroll
        for (int nb = 0; nb < 4; nb++)
            ldsm4t(b[nb], st + BOFF3 + (k16 * 16 + bK) * BPITCH3 + (warpN + nb * 16 + bN) * 2);
    };

    uint32_t a0[4][4], b0[4][4], a1[4][4], b1[4][4];

    issue(0, 0);
    asm volatile("cp.async.commit_group;" ::: "memory");
    issue(1, 64);
    asm volatile("cp.async.commit_group;" ::: "memory");
    asm volatile("cp.async.wait_group 1;" ::: "memory");
    __syncthreads();
    loadA(sb, 0, a0);
    loadB(sb, 0, b0);

    int st_idx = 0;
    for (int it = 0; it < nit; it++) {
        uint32_t st = sb + st_idx * STAGE3;

        loadA(st, 1, a1);
        loadB(st, 1, b1);
        #pragma unroll
        for (int mi = 0; mi < 4; mi++)
            #pragma unroll
            for (int nj = 0; nj < 8; nj++)
                MMA(acc[mi][nj], a0[mi], &b0[nj >> 1][(nj & 1) * 2]);

        loadA(st, 2, a0);
        loadB(st, 2, b0);
        #pragma unroll
        for (int mi = 0; mi < 4; mi++)
            #pragma unroll
            for (int nj = 0; nj < 8; nj++)
                MMA(acc[mi][nj], a1[mi], &b1[nj >> 1][(nj & 1) * 2]);

        loadA(st, 3, a1);
        loadB(st, 3, b1);
        #pragma unroll
        for (int mi = 0; mi < 4; mi++)
            #pragma unroll
            for (int nj = 0; nj < 8; nj++)
                MMA(acc[mi][nj], a0[mi], &b0[nj >> 1][(nj & 1) * 2]);

        int nxt = it + 2;
        int nstage = st_idx + 2; if (nstage >= NSTG3) nstage -= NSTG3;
        if (nxt < nit) issue(nstage, nxt * 64);
        asm volatile("cp.async.commit_group;" ::: "memory");
        if (it + 1 < nit) {
            asm volatile("cp.async.wait_group 1;" ::: "memory");
            __syncthreads();
            int s1 = st_idx + 1; if (s1 >= NSTG3) s1 -= NSTG3;
            uint32_t stn = sb + s1 * STAGE3;
            loadA(stn, 0, a0);
            loadB(stn, 0, b0);
        }
        #pragma unroll
        for (int mi = 0; mi < 4; mi++)
            #pragma unroll
            for (int nj = 0; nj < 8; nj++)
                MMA(acc[mi][nj], a1[mi], &b1[nj >> 1][(nj & 1) * 2]);

        if (++st_idx >= NSTG3) st_idx = 0;
    }

    #pragma unroll
    for (int mi = 0; mi < 4; mi++) {
        int r0 = rt * 128 + warpM + mi * 16 + (lid >> 2);
        int r1 = r0 + 8;
        float ri0 = (r0 < Nn) ? g_rowinv[r0] : 0.f;
        float ri1 = (r1 < Nn) ? g_rowinv[r1] : 0.f;
        #pragma unroll
        for (int nj = 0; nj < 8; nj++) {
            int n = ct * 128 + warpN + nj * 8 + (lid & 3) * 2;
            if (r0 < Nn) {
                float2 v = make_float2(acc[mi][nj][0] * ri0, acc[mi][nj][1] * ri0);
                *(float2*)&Aggp[(size_t)r0 * NT + n] = v;
            }
            if (r1 < Nn) {
                float2 v = make_float2(acc[mi][nj][2] * ri1, acc[mi][nj][3] * ri1);
                *(float2*)&Aggp[(size_t)r1 * NT + n] = v;
            }
        }
    }
}

// ---------------------------------------------------------------------------
// Kernel 6: epilogue (unchanged from R16).
// ---------------------------------------------------------------------------
__global__ void __launch_bounds__(128) epilogue_kernel(
    const float* __restrict__ E,
    const float* __restrict__ bgp, const float* __restrict__ bup,
    const float* __restrict__ lw, const float* __restrict__ lb,
    float* __restrict__ out)
{
    __shared__ float sBr[8][2];
    __shared__ float sBc[8][2];
    int n0 = blockIdx.x * 8;
    int tid = threadIdx.x;
    if (tid < 16) {
        int ln = tid >> 1, o = tid & 1; int n = n0 + ln; float v = 0.f;
        if (n < Nn) { for (int d = 0; d < 4; d++) v += E[n * 4 + d] * bgp[d * 4 + 2 + o]; }
        sBr[ln][o] = v;
    } else if (tid < 32) {
        int t = tid - 16, ln = t >> 1, o = t & 1; int n = n0 + ln; float v = 0.f;
        if (n < Nn) { for (int d = 0; d < 4; d++) v += E[n * 4 + d] * bup[d * 2 + o]; }
        sBc[ln][o] = v;
    }
    __syncthreads();

    int ln = tid >> 4, b = tid & 15;
    int n = n0 + ln;
    if (n >= Nn) return;
    float e0 = E[n * 4 + 0], e1 = E[n * 4 + 1], e2 = E[n * 4 + 2], e3 = E[n * 4 + 3];
    size_t base = (size_t)n * NT + b * 16;
    const float4* t0 = (const float4*)(g_T0 + base);
    const float4* g0 = (const float4*)(g_Agg + base);
    const float4* g1 = (const float4*)(g_Agg + (size_t)MP * NT + base);
    const float4* g2 = (const float4*)(g_Agg + 2 * (size_t)MP * NT + base);
    float S[16];
    #pragma unroll
    for (int q = 0; q < 4; q++) {
        float4 a = t0[q], bq = g0[q], c = g1[q], d = g2[q];
        S[q * 4 + 0] = a.x + bq.x + c.x + d.x;
        S[q * 4 + 1] = a.y + bq.y + c.y + d.y;
        S[q * 4 + 2] = a.z + bq.z + c.z + d.z;
        S[q * 4 + 3] = a.w + bq.w + c.w + d.w;
    }
    float gr[2], uc[2];
    #pragma unroll
    for (int o = 0; o < 2; o++) {
        gr[o] = sBr[ln][o] + e0 * S[o]     + e1 * S[4 + o]
                           + e2 * S[8 + o] + e3 * S[12 + o];
        uc[o] = sBc[ln][o] + e0 * S[2 + o]  + e1 * S[6 + o]
                           + e2 * S[10 + o] + e3 * S[14 + o];
    }
    float R0 = 1.f / (1.f + __expf(-gr[0]));
    float R1 = 1.f / (1.f + __expf(-gr[1]));
    float C0 = tanhf(uc[0]);
    float C1 = tanhf(uc[1]);
    float h0 = (1.f - R0) * C0;
    float h1 = (1.f - R1) * C1;
    float y = fmaxf(h0, 0.f) * lw[0] + fmaxf(h1, 0.f) * lw[1] + lb[0];
    out[(size_t)b * Nn + n] = y;
}

// ---------------------------------------------------------------------------
extern "C" void kernel_launch(void* const* d_in, const int* in_sizes, int n_in,
                              void* d_out, int out_size) {
    const float* x  = (const float*)d_in[0];
    const float* e  = (const float*)d_in[1];
    const float* wg = (const float*)d_in[2];
    const float* bg = (const float*)d_in[3];
    const float* wu = (const float*)d_in[4];
    const float* bu = (const float*)d_in[5];
    const float* lw = (const float*)d_in[6];
    const float* lb = (const float*)d_in[7];
    float* out = (float*)d_out;

    cudaFuncSetAttribute(gemm_mma_kernel,
                         cudaFuncAttributeMaxDynamicSharedMemorySize, SMEM_TOTAL3);

    normmax_kernel<<<(Nn + 255) / 256, 256>>>(e);
    scl_kernel<<<MP / 256, 256>>>(e);
    fused_prep_kernel<<<NTBLK + NTILE, 256>>>(x, wg, wu);
    rowsum_kernel<<<MP / 8, 256>>>();
    gemm_mma_kernel<<<dim3(MT, CT, KSLICES), 128, SMEM_TOTAL3>>>();
    epilogue_kernel<<<(Nn + 7) / 8, 128>>>(e, bg, bu, lw, lb, out);
}